// round 3
// baseline (speedup 1.0000x reference)
#include <cuda_runtime.h>
#include <cstdint>
#include <cstddef>

#define N_CTX 4096
#define D_MODEL 2048

// Scratch (no cudaMalloc allowed): X = E@qk, S = scores/probs, Y = P@E
__device__ float g_X[(size_t)N_CTX * D_MODEL];
__device__ float g_S[(size_t)N_CTX * N_CTX];
__device__ float g_Y[(size_t)N_CTX * D_MODEL];

// ---------------------------------------------------------------------------
// fp32 SGEMM, double-buffered smem: C[M,N] = A[M,K] * op(B)
//   B_TRANS   : B is [N,K] row-major, use B^T   (scores = X @ E^T)
//   CAUSAL_OUT: zero elements with col > row; skip blocks fully above diagonal
//   CAUSAL_K  : only accumulate k-tiles with k < rowBase+BM (P upper == 0)
// Tile 128x128x16, 256 threads, 8x8 per-thread microtile.
// One __syncthreads per k-tile; global loads overlapped with FFMA block.
// ---------------------------------------------------------------------------
template<bool B_TRANS, bool CAUSAL_OUT, bool CAUSAL_K>
__global__ void __launch_bounds__(256, 2)
sgemm_db(const float* __restrict__ A, const float* __restrict__ B,
         float* __restrict__ C, int M, int N, int K)
{
    constexpr int BM = 128, BN = 128, BK = 16;
    __shared__ float As[2][BK][BM];
    __shared__ float Bs[2][BK][BN];

    const int rowBase = blockIdx.y * BM;
    const int colBase = blockIdx.x * BN;
    const int tid = threadIdx.x;

    if (CAUSAL_OUT && colBase > rowBase + BM - 1) {
        // Fully above the diagonal: write zeros (P must be 0 there for K4).
        const float4 z = make_float4(0.f, 0.f, 0.f, 0.f);
        for (int i = tid; i < BM * BN / 4; i += 256) {
            int r = i >> 5;
            int c = (i & 31) << 2;
            *reinterpret_cast<float4*>(&C[(size_t)(rowBase + r) * N + colBase + c]) = z;
        }
        return;
    }

    const int numTiles = CAUSAL_K ? (rowBase + BM) / BK : (K / BK);

    // --- load-index setup ---------------------------------------------------
    const int ldr = tid >> 2;            // 0..63
    const int ldc = (tid & 3) << 2;      // 0,4,8,12
    const int bnr = tid >> 5;            // 0..7
    const int bnc = (tid & 31) << 2;     // 0..124

    float4 a0g, a1g, b0g, b1g;

    auto loadTile = [&](int kBase) {
        a0g = *reinterpret_cast<const float4*>(&A[(size_t)(rowBase + ldr)      * K + kBase + ldc]);
        a1g = *reinterpret_cast<const float4*>(&A[(size_t)(rowBase + ldr + 64) * K + kBase + ldc]);
        if (B_TRANS) {
            b0g = *reinterpret_cast<const float4*>(&B[(size_t)(colBase + ldr)      * K + kBase + ldc]);
            b1g = *reinterpret_cast<const float4*>(&B[(size_t)(colBase + ldr + 64) * K + kBase + ldc]);
        } else {
            b0g = *reinterpret_cast<const float4*>(&B[(size_t)(kBase + bnr)     * N + colBase + bnc]);
            b1g = *reinterpret_cast<const float4*>(&B[(size_t)(kBase + bnr + 8) * N + colBase + bnc]);
        }
    };

    auto storeTile = [&](int buf) {
        As[buf][ldc + 0][ldr] = a0g.x;  As[buf][ldc + 1][ldr] = a0g.y;
        As[buf][ldc + 2][ldr] = a0g.z;  As[buf][ldc + 3][ldr] = a0g.w;
        As[buf][ldc + 0][ldr + 64] = a1g.x;  As[buf][ldc + 1][ldr + 64] = a1g.y;
        As[buf][ldc + 2][ldr + 64] = a1g.z;  As[buf][ldc + 3][ldr + 64] = a1g.w;
        if (B_TRANS) {
            Bs[buf][ldc + 0][ldr] = b0g.x;  Bs[buf][ldc + 1][ldr] = b0g.y;
            Bs[buf][ldc + 2][ldr] = b0g.z;  Bs[buf][ldc + 3][ldr] = b0g.w;
            Bs[buf][ldc + 0][ldr + 64] = b1g.x;  Bs[buf][ldc + 1][ldr + 64] = b1g.y;
            Bs[buf][ldc + 2][ldr + 64] = b1g.z;  Bs[buf][ldc + 3][ldr + 64] = b1g.w;
        } else {
            *reinterpret_cast<float4*>(&Bs[buf][bnr][bnc])     = b0g;
            *reinterpret_cast<float4*>(&Bs[buf][bnr + 8][bnc]) = b1g;
        }
    };

    // --- main loop ----------------------------------------------------------
    const int tm = (tid >> 4) << 3;
    const int tn = (tid & 15) << 3;

    float acc[8][8];
    #pragma unroll
    for (int i = 0; i < 8; ++i)
        #pragma unroll
        for (int j = 0; j < 8; ++j) acc[i][j] = 0.f;

    loadTile(0);
    storeTile(0);
    __syncthreads();

    for (int t = 0; t < numTiles; ++t) {
        const int cur = t & 1;
        const bool more = (t + 1 < numTiles);
        if (more) loadTile((t + 1) * BK);   // LDGs issue; latency hidden by FFMAs

        #pragma unroll
        for (int kk = 0; kk < BK; ++kk) {
            float4 av0 = *reinterpret_cast<const float4*>(&As[cur][kk][tm]);
            float4 av1 = *reinterpret_cast<const float4*>(&As[cur][kk][tm + 4]);
            float4 bv0 = *reinterpret_cast<const float4*>(&Bs[cur][kk][tn]);
            float4 bv1 = *reinterpret_cast<const float4*>(&Bs[cur][kk][tn + 4]);
            float a[8] = {av0.x, av0.y, av0.z, av0.w, av1.x, av1.y, av1.z, av1.w};
            float b[8] = {bv0.x, bv0.y, bv0.z, bv0.w, bv1.x, bv1.y, bv1.z, bv1.w};
            #pragma unroll
            for (int i = 0; i < 8; ++i)
                #pragma unroll
                for (int j = 0; j < 8; ++j)
                    acc[i][j] = fmaf(a[i], b[j], acc[i][j]);
        }

        if (more) storeTile(cur ^ 1);       // other buffer; prior readers synced
        __syncthreads();
    }

    // --- epilogue -----------------------------------------------------------
    #pragma unroll
    for (int i = 0; i < 8; ++i) {
        const int gr = rowBase + tm + i;
        #pragma unroll
        for (int j4 = 0; j4 < 2; ++j4) {
            float4 v = make_float4(acc[i][j4 * 4 + 0], acc[i][j4 * 4 + 1],
                                   acc[i][j4 * 4 + 2], acc[i][j4 * 4 + 3]);
            if (CAUSAL_OUT) {
                const int gc = colBase + tn + j4 * 4;
                if (gc + 0 > gr) v.x = 0.f;
                if (gc + 1 > gr) v.y = 0.f;
                if (gc + 2 > gr) v.z = 0.f;
                if (gc + 3 > gr) v.w = 0.f;
            }
            *reinterpret_cast<float4*>(&C[(size_t)gr * N + colBase + tn + j4 * 4]) = v;
        }
    }
}

// ---------------------------------------------------------------------------
// In-place causal row softmax: row i uses columns [0, i]; columns > i stay 0.
// 2-pass: max reduce, then exp into registers + sum reduce + scaled writeback.
// ---------------------------------------------------------------------------
__global__ void __launch_bounds__(256)
softmax_rows(float* __restrict__ S)
{
    __shared__ float red[256];
    const int i = blockIdx.x;
    const int len = i + 1;
    float* row = S + (size_t)i * N_CTX;
    const int tid = threadIdx.x;

    float m = -1e30f;
    for (int j = tid; j < len; j += 256) m = fmaxf(m, row[j]);
    red[tid] = m;
    __syncthreads();
    #pragma unroll
    for (int s = 128; s > 0; s >>= 1) {
        if (tid < s) red[tid] = fmaxf(red[tid], red[tid + s]);
        __syncthreads();
    }
    m = red[0];
    __syncthreads();

    // exp into registers (<= 16 elements per thread for N_CTX=4096)
    float ev[16];
    int cnt = 0;
    float sum = 0.f;
    for (int j = tid; j < len; j += 256) {
        float e = __expf(row[j] - m);
        ev[cnt++] = e;
        sum += e;
    }
    red[tid] = sum;
    __syncthreads();
    #pragma unroll
    for (int s = 128; s > 0; s >>= 1) {
        if (tid < s) red[tid] += red[tid + s];
        __syncthreads();
    }
    const float inv = 1.0f / red[0];

    cnt = 0;
    for (int j = tid; j < len; j += 256) row[j] = ev[cnt++] * inv;
}

// ---------------------------------------------------------------------------
extern "C" void kernel_launch(void* const* d_in, const int* in_sizes, int n_in,
                              void* d_out, int out_size)
{
    const float* E  = (const float*)d_in[0];   // [4096, 2048]
    const float* qk = (const float*)d_in[1];   // [2048, 2048]
    const float* ov = (const float*)d_in[2];   // [2048, 2048]
    float* out = (float*)d_out;                // [4096, 2048]

    void *pX, *pS, *pY;
    cudaGetSymbolAddress(&pX, g_X);
    cudaGetSymbolAddress(&pS, g_S);
    cudaGetSymbolAddress(&pY, g_Y);
    float* X = (float*)pX;
    float* S = (float*)pS;
    float* Y = (float*)pY;

    dim3 blk(256);

    // K1: X = E @ qk
    sgemm_db<false, false, false><<<dim3(D_MODEL / 128, N_CTX / 128), blk>>>(
        E, qk, X, N_CTX, D_MODEL, D_MODEL);

    // K2: S = X @ E^T, causal-masked
    sgemm_db<true, true, false><<<dim3(N_CTX / 128, N_CTX / 128), blk>>>(
        X, E, S, N_CTX, N_CTX, D_MODEL);

    // K3: in-place causal softmax per row
    softmax_rows<<<N_CTX, blk>>>(S);

    // K4: Y = P @ E (k-tiles limited to row block end; P upper is 0)
    sgemm_db<false, false, true><<<dim3(D_MODEL / 128, N_CTX / 128), blk>>>(
        S, E, Y, N_CTX, D_MODEL, N_CTX);

    // K5: out = Y @ ov
    sgemm_db<false, false, false><<<dim3(D_MODEL / 128, N_CTX / 128), blk>>>(
        Y, ov, out, N_CTX, D_MODEL, D_MODEL);
}

// round 6
// speedup vs baseline: 1.1972x; 1.1972x over previous
#include <cuda_runtime.h>
#include <cstdint>
#include <cstddef>

#define N_CTX 4096
#define D_MODEL 2048

// Scratch: X = E@qk, S = scores/probs, Y = P@E
__device__ float g_X[(size_t)N_CTX * D_MODEL];
__device__ float g_S[(size_t)N_CTX * N_CTX];
__device__ float g_Y[(size_t)N_CTX * D_MODEL];

__device__ __forceinline__ float tf32_rn(float x) {
    uint32_t u;
    asm("cvt.rna.tf32.f32 %0, %1;" : "=r"(u) : "f"(x));
    return __uint_as_float(u);
}

// m16n8k8 tf32 MMA, fp32 accumulate (base PTX, no 'a' features)
__device__ __forceinline__ void mma8(float c[4], const uint32_t a[4], const uint32_t b[2]) {
    asm volatile(
        "mma.sync.aligned.m16n8k8.row.col.f32.tf32.tf32.f32 "
        "{%0,%1,%2,%3}, {%4,%5,%6,%7}, {%8,%9}, {%0,%1,%2,%3};"
        : "+f"(c[0]), "+f"(c[1]), "+f"(c[2]), "+f"(c[3])
        : "r"(a[0]), "r"(a[1]), "r"(a[2]), "r"(a[3]), "r"(b[0]), "r"(b[1]));
}

// ---------------------------------------------------------------------------
// tf32x3 warp-MMA GEMM: C[M,N] = A[M,K] * op(B), 128x128 CTA tile, 512 thr.
//   B_TRANS   : B is [N,K] row-major (use B^T)
//   CAUSAL_OUT: zero col>row; skip blocks fully above diagonal
//   CAUSAL_K  : only K-chunks < rowBase+128 (P upper is zero)
// Warp grid 4x4, warp tile 32x32 (2 mtiles x 4 ntiles of m16n8).
// Smem: A,[B^T] as [m/n][k] stride 20 (conflict-free frags);
//       B-NN as [k][n] stride 136 (conflict-free frags + float4 stores).
// ---------------------------------------------------------------------------
template<bool B_TRANS, bool CAUSAL_OUT, bool CAUSAL_K>
__global__ void __launch_bounds__(512, 1)
mma_gemm(const float* __restrict__ A, const float* __restrict__ B,
         float* __restrict__ C, int N, int K)
{
    constexpr int BK = 16;
    __shared__ float As_h[128 * 20], As_l[128 * 20];
    __shared__ float Bs_h[128 * 20], Bs_l[128 * 20];   // NN path uses 16*136

    const int tid  = threadIdx.x;
    const int wid  = tid >> 5;
    const int lane = tid & 31;
    const int g    = lane >> 2;      // 0..7
    const int tig  = lane & 3;       // 0..3
    const int warpM = wid & 3;       // 4 along M (32 rows each)
    const int warpN = wid >> 2;      // 4 along N (32 cols each)

    const int rowBase = blockIdx.y * 128;
    const int colBase = blockIdx.x * 128;

    if (CAUSAL_OUT && colBase > rowBase + 127) {
        const float4 z = make_float4(0.f, 0.f, 0.f, 0.f);
        for (int i = tid; i < 128 * 32; i += 512) {
            int r = i >> 5, c = (i & 31) << 2;
            *reinterpret_cast<float4*>(&C[(size_t)(rowBase + r) * N + colBase + c]) = z;
        }
        return;
    }

    const int numTiles = CAUSAL_K ? (rowBase + 128) / BK : (K / BK);

    // global-load indices (512 threads)
    const int arow = tid >> 2;          // 0..127
    const int aq   = tid & 3;           // 0..3  (float4 along K)
    const int bkr  = tid >> 5;          // 0..15 (NN: K row)
    const int bnq  = tid & 31;          // 0..31 (NN: float4 along N)

    float4 va, vb;
    auto gload = [&](int t) {
        const int kBase = t * BK;
        va = *reinterpret_cast<const float4*>(&A[(size_t)(rowBase + arow) * K + kBase + aq * 4]);
        if (B_TRANS)
            vb = *reinterpret_cast<const float4*>(&B[(size_t)(colBase + arow) * K + kBase + aq * 4]);
        else
            vb = *reinterpret_cast<const float4*>(&B[(size_t)(kBase + bkr) * N + colBase + bnq * 4]);
    };

    auto sstore = [&]() {
        float hx = tf32_rn(va.x), hy = tf32_rn(va.y), hz = tf32_rn(va.z), hw = tf32_rn(va.w);
        int ao = arow * 20 + aq * 4;
        *reinterpret_cast<float4*>(&As_h[ao]) = make_float4(hx, hy, hz, hw);
        *reinterpret_cast<float4*>(&As_l[ao]) = make_float4(
            tf32_rn(va.x - hx), tf32_rn(va.y - hy), tf32_rn(va.z - hz), tf32_rn(va.w - hw));
        float bx = tf32_rn(vb.x), by = tf32_rn(vb.y), bz = tf32_rn(vb.z), bw = tf32_rn(vb.w);
        float lx = tf32_rn(vb.x - bx), ly = tf32_rn(vb.y - by),
              lz = tf32_rn(vb.z - bz), lw = tf32_rn(vb.w - bw);
        if (B_TRANS) {
            *reinterpret_cast<float4*>(&Bs_h[ao]) = make_float4(bx, by, bz, bw);
            *reinterpret_cast<float4*>(&Bs_l[ao]) = make_float4(lx, ly, lz, lw);
        } else {
            int bo = bkr * 136 + bnq * 4;
            *reinterpret_cast<float4*>(&Bs_h[bo]) = make_float4(bx, by, bz, bw);
            *reinterpret_cast<float4*>(&Bs_l[bo]) = make_float4(lx, ly, lz, lw);
        }
    };

    float acc[2][4][4];
    #pragma unroll
    for (int i = 0; i < 2; ++i)
        #pragma unroll
        for (int j = 0; j < 4; ++j)
            #pragma unroll
            for (int r = 0; r < 4; ++r) acc[i][j][r] = 0.f;

    gload(0);
    for (int t = 0; t < numTiles; ++t) {
        sstore();
        __syncthreads();
        if (t + 1 < numTiles) gload(t + 1);

        #pragma unroll
        for (int k0 = 0; k0 < BK; k0 += 8) {
            uint32_t ah[2][4], al[2][4], bh[4][2], bl[4][2];
            #pragma unroll
            for (int i = 0; i < 2; ++i) {
                int base = (warpM * 32 + i * 16 + g) * 20 + k0 + tig;
                ah[i][0] = __float_as_uint(As_h[base]);
                ah[i][1] = __float_as_uint(As_h[base + 160]);
                ah[i][2] = __float_as_uint(As_h[base + 4]);
                ah[i][3] = __float_as_uint(As_h[base + 164]);
                al[i][0] = __float_as_uint(As_l[base]);
                al[i][1] = __float_as_uint(As_l[base + 160]);
                al[i][2] = __float_as_uint(As_l[base + 4]);
                al[i][3] = __float_as_uint(As_l[base + 164]);
            }
            #pragma unroll
            for (int j = 0; j < 4; ++j) {
                if (B_TRANS) {
                    int base = (warpN * 32 + j * 8 + g) * 20 + k0 + tig;
                    bh[j][0] = __float_as_uint(Bs_h[base]);
                    bh[j][1] = __float_as_uint(Bs_h[base + 4]);
                    bl[j][0] = __float_as_uint(Bs_l[base]);
                    bl[j][1] = __float_as_uint(Bs_l[base + 4]);
                } else {
                    int base = (k0 + tig) * 136 + warpN * 32 + j * 8 + g;
                    bh[j][0] = __float_as_uint(Bs_h[base]);
                    bh[j][1] = __float_as_uint(Bs_h[base + 4 * 136]);
                    bl[j][0] = __float_as_uint(Bs_l[base]);
                    bl[j][1] = __float_as_uint(Bs_l[base + 4 * 136]);
                }
            }
            #pragma unroll
            for (int i = 0; i < 2; ++i)
                #pragma unroll
                for (int j = 0; j < 4; ++j) {
                    mma8(acc[i][j], ah[i], bh[j]);
                    mma8(acc[i][j], ah[i], bl[j]);
                    mma8(acc[i][j], al[i], bh[j]);
                }
        }
        __syncthreads();
    }

    // epilogue: c0,c1 -> (row, col..col+1), c2,c3 -> (row+8, ...)
    #pragma unroll
    for (int i = 0; i < 2; ++i) {
        const int gr0 = rowBase + warpM * 32 + i * 16 + g;
        #pragma unroll
        for (int j = 0; j < 4; ++j) {
            const int gc = colBase + warpN * 32 + j * 8 + tig * 2;
            float2 v0 = make_float2(acc[i][j][0], acc[i][j][1]);
            float2 v1 = make_float2(acc[i][j][2], acc[i][j][3]);
            if (CAUSAL_OUT) {
                if (gc + 0 > gr0) v0.x = 0.f;
                if (gc + 1 > gr0) v0.y = 0.f;
                if (gc + 0 > gr0 + 8) v1.x = 0.f;
                if (gc + 1 > gr0 + 8) v1.y = 0.f;
            }
            *reinterpret_cast<float2*>(&C[(size_t)gr0 * N + gc]) = v0;
            *reinterpret_cast<float2*>(&C[(size_t)(gr0 + 8) * N + gc]) = v1;
        }
    }
}

// ---------------------------------------------------------------------------
// In-place causal row softmax (row i uses cols [0,i]; cols > i remain 0).
// ---------------------------------------------------------------------------
__global__ void __launch_bounds__(256)
softmax_rows(float* __restrict__ S)
{
    __shared__ float red[256];
    const int i = blockIdx.x;
    const int len = i + 1;
    float* row = S + (size_t)i * N_CTX;
    const int tid = threadIdx.x;

    float m = -1e30f;
    for (int j = tid; j < len; j += 256) m = fmaxf(m, row[j]);
    red[tid] = m;
    __syncthreads();
    #pragma unroll
    for (int s = 128; s > 0; s >>= 1) {
        if (tid < s) red[tid] = fmaxf(red[tid], red[tid + s]);
        __syncthreads();
    }
    m = red[0];
    __syncthreads();

    float ev[16];
    int cnt = 0;
    float sum = 0.f;
    for (int j = tid; j < len; j += 256) {
        float e = __expf(row[j] - m);
        ev[cnt++] = e;
        sum += e;
    }
    red[tid] = sum;
    __syncthreads();
    #pragma unroll
    for (int s = 128; s > 0; s >>= 1) {
        if (tid < s) red[tid] += red[tid + s];
        __syncthreads();
    }
    const float inv = 1.0f / red[0];

    cnt = 0;
    for (int j = tid; j < len; j += 256) row[j] = ev[cnt++] * inv;
}

// ---------------------------------------------------------------------------
extern "C" void kernel_launch(void* const* d_in, const int* in_sizes, int n_in,
                              void* d_out, int out_size)
{
    const float* E  = (const float*)d_in[0];   // [4096, 2048]
    const float* qk = (const float*)d_in[1];   // [2048, 2048]
    const float* ov = (const float*)d_in[2];   // [2048, 2048]
    float* out = (float*)d_out;                // [4096, 2048]

    void *pX, *pS, *pY;
    cudaGetSymbolAddress(&pX, g_X);
    cudaGetSymbolAddress(&pS, g_S);
    cudaGetSymbolAddress(&pY, g_Y);
    float* X = (float*)pX;
    float* S = (float*)pS;
    float* Y = (float*)pY;

    dim3 blk(512);

    // K1: X = E @ qk        (B = qk is [K,N] -> k-major smem path)
    mma_gemm<false, false, false><<<dim3(D_MODEL / 128, N_CTX / 128), blk>>>(
        E, qk, X, D_MODEL, D_MODEL);

    // K2: S = X @ E^T       (B = E is [N,K] natural), causal epilogue
    mma_gemm<true, true, false><<<dim3(N_CTX / 128, N_CTX / 128), blk>>>(
        X, E, S, N_CTX, D_MODEL);

    // K3: causal softmax
    softmax_rows<<<N_CTX, dim3(256)>>>(S);

    // K4: Y = P @ E         (B = E is [K,N]; causal K-chunk skip)
    mma_gemm<false, false, true><<<dim3(D_MODEL / 128, N_CTX / 128), blk>>>(
        S, E, Y, D_MODEL, N_CTX);

    // K5: out = Y @ ov      (B = ov is [K,N])
    mma_gemm<false, false, false><<<dim3(D_MODEL / 128, N_CTX / 128), blk>>>(
        Y, ov, out, D_MODEL, D_MODEL);
}